// round 5
// baseline (speedup 1.0000x reference)
#include <cuda_runtime.h>
#include <cuda_bf16.h>
#include <cstdint>

// out[g] = sigmoid(Z_g @ Z_g^T), G=128, N=512, D=256, fp32.
// mma.sync.m16n8k16 bf16, hi/lo split (hh + lh + hl products).
// R5: remove WAR on B fragments (separate bh/bl regs), hoist LDSM, 3
// independent MMA sweeps, 1 sync/chunk, diagonal tiles alias B->A smem.

namespace {
constexpr int NN = 512;
constexpr int ND = 256;
constexpr int BM = 128;
constexpr int NPAIR = 10;
constexpr int BKC = 32;                  // k per chunk
constexpr int NCH = ND / BKC;            // 8 chunks
constexpr int SMATC = BM * BKC * 2;      // 8192 B per operand per chunk
constexpr int SSTAGE = 4 * SMATC;        // 32768 B (Ah, Al, Bh, Bl)
constexpr int NSTAGE = 3;
constexpr int SMEM_DYN = NSTAGE * SSTAGE;  // 98304 B
}

__constant__ int c_it[NPAIR] = {0,0,0,0,1,1,1,2,2,3};
__constant__ int c_jt[NPAIR] = {0,1,2,3,1,2,3,2,3,3};

__device__ __align__(16) __nv_bfloat16 g_zh[(size_t)128 * 512 * 256];  // 32MB
__device__ __align__(16) __nv_bfloat16 g_zl[(size_t)128 * 512 * 256];  // 32MB

__device__ __forceinline__ uint32_t cvta_smem(const void* p) {
    uint32_t a;
    asm("{ .reg .u64 t; cvta.to.shared.u64 t, %1; cvt.u32.u64 %0, t; }"
        : "=r"(a) : "l"(p));
    return a;
}

// swizzled byte offset within one operand mat: 64B rows, 4 x 16B segs
__device__ __forceinline__ uint32_t swz(int row, int seg) {
    return (uint32_t)(row * 64 + ((seg ^ ((row >> 1) & 3)) << 4));
}

__device__ __forceinline__ void ldsm4(uint32_t* r, uint32_t addr) {
    asm volatile("ldmatrix.sync.aligned.m8n8.x4.shared.b16 {%0,%1,%2,%3}, [%4];"
                 : "=r"(r[0]), "=r"(r[1]), "=r"(r[2]), "=r"(r[3]) : "r"(addr));
}

__device__ __forceinline__ void mma16816(float* c, const uint32_t* a,
                                         uint32_t b0, uint32_t b1) {
    asm volatile(
        "mma.sync.aligned.m16n8k16.row.col.f32.bf16.bf16.f32 "
        "{%0,%1,%2,%3}, {%4,%5,%6,%7}, {%8,%9}, {%0,%1,%2,%3};"
        : "+f"(c[0]), "+f"(c[1]), "+f"(c[2]), "+f"(c[3])
        : "r"(a[0]), "r"(a[1]), "r"(a[2]), "r"(a[3]), "r"(b0), "r"(b1));
}

__device__ __forceinline__ float fast_sigmoid(float x) {
    float e = __expf(-x);
    return __fdividef(1.0f, 1.0f + e);
}

// ---------------- pre-pass: fp32 -> bf16 hi/lo ----------------
__global__ __launch_bounds__(256)
void convert_kernel(const float* __restrict__ z) {
    size_t base = ((size_t)blockIdx.x * blockDim.x + threadIdx.x) * 2;
#pragma unroll
    for (int u = 0; u < 2; u++) {
        size_t i = base + u;
        float4 v = ((const float4*)z)[i];
        __nv_bfloat162 h01 = __floats2bfloat162_rn(v.x, v.y);
        __nv_bfloat162 h23 = __floats2bfloat162_rn(v.z, v.w);
        float2 f01 = __bfloat1622float2(h01);
        float2 f23 = __bfloat1622float2(h23);
        __nv_bfloat162 l01 = __floats2bfloat162_rn(v.x - f01.x, v.y - f01.y);
        __nv_bfloat162 l23 = __floats2bfloat162_rn(v.z - f23.x, v.w - f23.y);
        ((uint2*)g_zh)[i] = make_uint2(*(uint32_t*)&h01, *(uint32_t*)&h23);
        ((uint2*)g_zl)[i] = make_uint2(*(uint32_t*)&l01, *(uint32_t*)&l23);
    }
}

// ---------------- GEMM + sigmoid ----------------
__global__ __launch_bounds__(256, 2)
void gemm_kernel(float* __restrict__ out) {
    extern __shared__ char smem[];
    const int tid  = threadIdx.x;
    const int lane = tid & 31;
    const int wid  = tid >> 5;
    const int wm   = wid & 3;   // 32-row block
    const int wn   = wid >> 2;  // 64-col block

    const int g  = blockIdx.y;
    const int it = c_it[blockIdx.x];
    const int jt = c_jt[blockIdx.x];
    const bool diag = (it == jt);

    const __nv_bfloat16* __restrict__ Ah = g_zh + ((size_t)g * NN + it * BM) * ND;
    const __nv_bfloat16* __restrict__ Al = g_zl + ((size_t)g * NN + it * BM) * ND;
    const __nv_bfloat16* __restrict__ Bh = g_zh + ((size_t)g * NN + jt * BM) * ND;
    const __nv_bfloat16* __restrict__ Bl = g_zl + ((size_t)g * NN + jt * BM) * ND;

    const uint32_t s32 = cvta_smem(smem);
    // diagonal tiles: B aliases A (skip loading mats 2,3)
    const uint32_t bh_base = diag ? 0u : 2u * SMATC;
    const uint32_t bl_base = diag ? 1u * SMATC : 3u * SMATC;
    const int nmat = diag ? 2 : 4;

    const int ld_row0 = tid >> 2;
    const int ld_seg  = tid & 3;

    float c[2][8][4];
#pragma unroll
    for (int mt = 0; mt < 2; mt++)
#pragma unroll
        for (int nt = 0; nt < 8; nt++)
#pragma unroll
            for (int q = 0; q < 4; q++) c[mt][nt][q] = 0.0f;

    const int la_r = lane & 15, la_s = lane >> 4;
    const int lb_r = ((lane >> 4) << 3) + (lane & 7), lb_s = (lane >> 3) & 1;

    auto issue_chunk = [&](int ch) {
        const uint32_t sb = s32 + (ch % NSTAGE) * SSTAGE;
        const int kofs = ch * BKC;
        for (int mat = 0; mat < nmat; mat++) {
            const __nv_bfloat16* src =
                (mat == 0) ? Ah : (mat == 1) ? Al : (mat == 2) ? Bh : Bl;
            const uint32_t mb = sb + mat * SMATC;
#pragma unroll
            for (int i2 = 0; i2 < 2; i2++) {
                const int row = ld_row0 + 64 * i2;
                const uint32_t dst = mb + swz(row, ld_seg);
                const void* s = src + (size_t)row * ND + kofs + ld_seg * 8;
                asm volatile("cp.async.cg.shared.global [%0], [%1], 16;"
                             :: "r"(dst), "l"(s) : "memory");
            }
        }
    };

    // prologue: chunks 0,1
    issue_chunk(0);
    asm volatile("cp.async.commit_group;" ::: "memory");
    issue_chunk(1);
    asm volatile("cp.async.commit_group;" ::: "memory");

    for (int ch = 0; ch < NCH; ch++) {
        asm volatile("cp.async.wait_group 1;" ::: "memory");
        __syncthreads();
        if (ch + 2 < NCH) issue_chunk(ch + 2);
        asm volatile("cp.async.commit_group;" ::: "memory");

        const uint32_t sb = s32 + (ch % NSTAGE) * SSTAGE;
#pragma unroll
        for (int h = 0; h < 2; h++) {
            uint32_t ah[2][4], al[2][4], bh[16], bl[16];
            // hoisted loads: 12 LDSM, no WAR within half-step
#pragma unroll
            for (int mt = 0; mt < 2; mt++) {
                const int row = wm * 32 + mt * 16 + la_r;
                const int seg = 2 * h + la_s;
                ldsm4(ah[mt], sb + 0 * SMATC + swz(row, seg));
                ldsm4(al[mt], sb + 1 * SMATC + swz(row, seg));
            }
#pragma unroll
            for (int bt = 0; bt < 4; bt++) {
                const int row = wn * 64 + bt * 16 + lb_r;
                const int seg = 2 * h + lb_s;
                ldsm4(&bh[bt * 4], sb + bh_base + swz(row, seg));
                ldsm4(&bl[bt * 4], sb + bl_base + swz(row, seg));
            }
            // sweep 1: Ah * Bh
#pragma unroll
            for (int mt = 0; mt < 2; mt++)
#pragma unroll
                for (int nt = 0; nt < 8; nt++) {
                    const int bi = (nt >> 1) * 4 + (nt & 1) * 2;
                    mma16816(c[mt][nt], ah[mt], bh[bi], bh[bi + 1]);
                }
            // sweep 2: Al * Bh
#pragma unroll
            for (int mt = 0; mt < 2; mt++)
#pragma unroll
                for (int nt = 0; nt < 8; nt++) {
                    const int bi = (nt >> 1) * 4 + (nt & 1) * 2;
                    mma16816(c[mt][nt], al[mt], bh[bi], bh[bi + 1]);
                }
            // sweep 3: Ah * Bl
#pragma unroll
            for (int mt = 0; mt < 2; mt++)
#pragma unroll
                for (int nt = 0; nt < 8; nt++) {
                    const int bi = (nt >> 1) * 4 + (nt & 1) * 2;
                    mma16816(c[mt][nt], ah[mt], bl[bi], bl[bi + 1]);
                }
        }
    }

    // ---- epilogue: sigmoid -> smem -> coalesced direct + transposed stores ----
    __syncthreads();
    float* sC = (float*)smem;  // [128][132] fp32 = 67584 B <= 98304 B
    const int r0  = wm * 32 + (lane >> 2);
    const int cn0 = wn * 64 + (lane & 3) * 2;
#pragma unroll
    for (int mt = 0; mt < 2; mt++)
#pragma unroll
        for (int nt = 0; nt < 8; nt++) {
            const int r  = r0 + mt * 16;
            const int cc = cn0 + nt * 8;
            sC[r * 132 + cc]           = fast_sigmoid(c[mt][nt][0]);
            sC[r * 132 + cc + 1]       = fast_sigmoid(c[mt][nt][1]);
            sC[(r + 8) * 132 + cc]     = fast_sigmoid(c[mt][nt][2]);
            sC[(r + 8) * 132 + cc + 1] = fast_sigmoid(c[mt][nt][3]);
        }
    __syncthreads();

    const int rbase = it * BM, cbase = jt * BM;
    {
        const int r    = tid >> 1;
        const int colh = (tid & 1) * 64;
        float* dst = out + ((size_t)g * NN + rbase + r) * NN + cbase + colh;
        const float* srcr = sC + r * 132 + colh;
#pragma unroll
        for (int q = 0; q < 16; q++)
            ((float4*)dst)[q] = ((const float4*)srcr)[q];
    }
    if (!diag) {
        const int cc = tid >> 1;
        const int rh = (tid & 1) * 64;
        float* dst = out + ((size_t)g * NN + cbase + cc) * NN + rbase + rh;
#pragma unroll
        for (int q = 0; q < 16; q++) {
            float4 w;
            w.x = sC[(rh + q * 4 + 0) * 132 + cc];
            w.y = sC[(rh + q * 4 + 1) * 132 + cc];
            w.z = sC[(rh + q * 4 + 2) * 132 + cc];
            w.w = sC[(rh + q * 4 + 3) * 132 + cc];
            ((float4*)dst)[q] = w;
        }
    }
}

extern "C" void kernel_launch(void* const* d_in, const int* in_sizes, int n_in,
                              void* d_out, int out_size) {
    const float* z = (const float*)d_in[0];
    float* out = (float*)d_out;
    convert_kernel<<<8192, 256>>>(z);
    cudaFuncSetAttribute(gemm_kernel, cudaFuncAttributeMaxDynamicSharedMemorySize,
                         SMEM_DYN);
    dim3 grid(NPAIR, 128);
    gemm_kernel<<<grid, 256, SMEM_DYN>>>(out);
}